// round 17
// baseline (speedup 1.0000x reference)
#include <cuda_runtime.h>
#include <cuda_bf16.h>
#include <cstdint>

#define BB 64
#define TT 512
#define HH 300
#define VV 50257

// Scratch (allocation-free: __device__ globals)
__device__ float g_ux[BB * TT * HH];   // [B*T, H] input projections
__device__ float g_h[BB * HH];         // final hidden state

// ---- shared HMMA helpers (proven in R15 k1) ----
#define PITCH_B 144

__device__ __forceinline__ void mma16816(float* c, const uint32_t* a,
                                         uint32_t b0, uint32_t b1) {
    asm volatile(
        "mma.sync.aligned.m16n8k16.row.col.f32.bf16.bf16.f32 "
        "{%0,%1,%2,%3}, {%4,%5,%6,%7}, {%8,%9}, {%0,%1,%2,%3};"
        : "+f"(c[0]), "+f"(c[1]), "+f"(c[2]), "+f"(c[3])
        : "r"(a[0]), "r"(a[1]), "r"(a[2]), "r"(a[3]), "r"(b0), "r"(b1));
}

__device__ __forceinline__ uint32_t pack_bf16(float a, float b) {
    __nv_bfloat162 h = __floats2bfloat162_rn(a, b);
    return *reinterpret_cast<uint32_t*>(&h);
}

// hi/lo bf16 split of a float4 -> two packed uint2
__device__ __forceinline__ void split4(const float4& v, uint2& hi, uint2& lo) {
    float h0 = __bfloat162float(__float2bfloat16_rn(v.x));
    float h1 = __bfloat162float(__float2bfloat16_rn(v.y));
    float h2 = __bfloat162float(__float2bfloat16_rn(v.z));
    float h3 = __bfloat162float(__float2bfloat16_rn(v.w));
    hi = make_uint2(pack_bf16(h0, h1), pack_bf16(h2, h3));
    lo = make_uint2(pack_bf16(v.x - h0, v.y - h1), pack_bf16(v.z - h2, v.w - h3));
}

// =====================================================================
// Kernel 1 (HMMA, R15-proven byte-identical): ux[m,g] = emb[tok[m]]·U[g]
// =====================================================================
#define K1_AH 0
#define K1_AL 18432
#define K1_BH 36864
#define K1_BL 80640
#define K1_BYTES (124416 + 128)

__global__ void __launch_bounds__(256, 1) k_embed_ux_mma(
    const int* __restrict__ tokens, const float* __restrict__ emb,
    const float* __restrict__ U)
{
    extern __shared__ char dsm_raw[];
    __shared__ int ts[128];

    const int t    = threadIdx.x;
    const int w    = t >> 5;
    const int lane = t & 31;
    const int r    = lane >> 2;
    const int tig  = lane & 3;
    const int m0   = blockIdx.x * 128;

    uintptr_t rawp = (uintptr_t)dsm_raw;
    char* dsm = dsm_raw + (((rawp + 127u) & ~(uintptr_t)127u) - rawp);

    if (t < 128) ts[t] = tokens[m0 + t];

    float acc[38][4];
#pragma unroll
    for (int nt = 0; nt < 38; nt++)
#pragma unroll
        for (int j = 0; j < 4; j++) acc[nt][j] = 0.f;

    for (int c = 0; c < 5; c++) {
        const int k0 = c * 64;
        __syncthreads();

        for (int idx = t; idx < 128 * 16; idx += 256) {
            const int row  = idx >> 4;
            const int c4   = idx & 15;
            const int gcol = k0 + c4 * 4;
            float4 v = make_float4(0.f, 0.f, 0.f, 0.f);
            if (gcol <= HH - 4)
                v = *(const float4*)(emb + (size_t)ts[row] * HH + gcol);
            uint2 hi, lo;
            split4(v, hi, lo);
            const int off = row * PITCH_B + c4 * 8;
            *(uint2*)(dsm + K1_AH + off) = hi;
            *(uint2*)(dsm + K1_AL + off) = lo;
        }
        for (int idx = t; idx < 304 * 16; idx += 256) {
            const int row  = idx >> 4;
            const int c4   = idx & 15;
            const int gcol = k0 + c4 * 4;
            float4 v = make_float4(0.f, 0.f, 0.f, 0.f);
            if (row < HH && gcol <= HH - 4)
                v = *(const float4*)(U + (size_t)row * HH + gcol);
            uint2 hi, lo;
            split4(v, hi, lo);
            const int off = row * PITCH_B + c4 * 8;
            *(uint2*)(dsm + K1_BH + off) = hi;
            *(uint2*)(dsm + K1_BL + off) = lo;
        }
        __syncthreads();

#pragma unroll
        for (int ks = 0; ks < 4; ks++) {
            const int koff = ks * 32 + tig * 4;
            const int arow = (w * 16 + r) * PITCH_B;
            uint32_t ah[4], al[4];
            ah[0] = *(const uint32_t*)(dsm + K1_AH + arow + koff);
            ah[1] = *(const uint32_t*)(dsm + K1_AH + arow + 8 * PITCH_B + koff);
            ah[2] = *(const uint32_t*)(dsm + K1_AH + arow + koff + 16);
            ah[3] = *(const uint32_t*)(dsm + K1_AH + arow + 8 * PITCH_B + koff + 16);
            al[0] = *(const uint32_t*)(dsm + K1_AL + arow + koff);
            al[1] = *(const uint32_t*)(dsm + K1_AL + arow + 8 * PITCH_B + koff);
            al[2] = *(const uint32_t*)(dsm + K1_AL + arow + koff + 16);
            al[3] = *(const uint32_t*)(dsm + K1_AL + arow + 8 * PITCH_B + koff + 16);
#pragma unroll
            for (int nt = 0; nt < 38; nt++) {
                const int brow = (nt * 8 + r) * PITCH_B;
                uint32_t bh0 = *(const uint32_t*)(dsm + K1_BH + brow + koff);
                uint32_t bh1 = *(const uint32_t*)(dsm + K1_BH + brow + koff + 16);
                uint32_t bl0 = *(const uint32_t*)(dsm + K1_BL + brow + koff);
                uint32_t bl1 = *(const uint32_t*)(dsm + K1_BL + brow + koff + 16);
                mma16816(acc[nt], ah, bh0, bh1);
                mma16816(acc[nt], al, bh0, bh1);
                mma16816(acc[nt], ah, bl0, bl1);
            }
        }
    }

    const int row0 = m0 + w * 16 + r;
#pragma unroll
    for (int nt = 0; nt < 38; nt++) {
        const int col = nt * 8 + 2 * tig;
        if (col < HH) {
            *(float2*)(g_ux + (size_t)row0 * HH + col) =
                make_float2(acc[nt][0], acc[nt][1]);
            *(float2*)(g_ux + (size_t)(row0 + 8) * HH + col) =
                make_float2(acc[nt][2], acc[nt][3]);
        }
    }
}

// =====================================================================
// Kernel 2: recurrence (R6-proven, byte-identical).  2-CTA cluster per
// batch element; monotonic DSMEM flag handshake.
// =====================================================================
__global__ void __launch_bounds__(320, 1) __cluster_dims__(2, 1, 1)
k_scan(const float* __restrict__ W, const float* __restrict__ ihs)
{
    __shared__ float hbuf[2][304];
    __shared__ unsigned int flag;

    const int t    = threadIdx.x;
    const int r    = blockIdx.x & 1;
    const int b    = blockIdx.x >> 1;
    const int o_l  = t >> 1;
    const int half = t & 1;

    const int Lb     = r ? 152 : 0;
    const int Pb     = r ? 0 : 152;
    const int myLen  = r ? 148 : 152;
    const bool active = (o_l < myLen);
    const int o_g    = Lb + o_l;

    const int wLbase = Lb + half * 76;
    const int wPbase = Pb + half * 76;

    float wl[76], wp[76];
#pragma unroll
    for (int j = 0; j < 76; j++) {
        const int kL = wLbase + j;
        const int kP = wPbase + j;
        wl[j] = (active && kL < HH) ? W[(size_t)o_g * HH + kL] : 0.f;
        wp[j] = (active && kP < HH) ? W[(size_t)o_g * HH + kP] : 0.f;
    }

    if (t < 304) {
        hbuf[0][t] = (t < HH) ? ihs[b * HH + t] : 0.f;
        hbuf[1][t] = 0.f;
    }
    if (t == 0) flag = 0u;

    uint32_t my_h0, my_fl;
    {
        uint64_t a;
        asm("cvta.to.shared.u64 %0, %1;" : "=l"(a) : "l"(&hbuf[0][0]));
        my_h0 = (uint32_t)a;
        asm("cvta.to.shared.u64 %0, %1;" : "=l"(a) : "l"(&flag));
        my_fl = (uint32_t)a;
    }
    uint32_t ph0, pfl;
    asm("mapa.shared::cluster.u32 %0, %1, %2;" : "=r"(ph0) : "r"(my_h0), "r"(r ^ 1));
    asm("mapa.shared::cluster.u32 %0, %1, %2;" : "=r"(pfl) : "r"(my_fl), "r"(r ^ 1));
    const uint32_t pdst0 = ph0 + (uint32_t)o_g * 4u;
    const uint32_t pdst1 = ph0 + 304u * 4u + (uint32_t)o_g * 4u;

    asm volatile("barrier.cluster.arrive.aligned;" ::: "memory");
    asm volatile("barrier.cluster.wait.aligned;"   ::: "memory");

    const float* uxp = g_ux + (size_t)b * TT * HH;
    float hn  = 0.f;
    float uxv = active ? __ldg(uxp + o_g) : 0.f;

    for (int step = 0; step < TT; step++) {
        const int cb = step & 1;
        const float* hp = &hbuf[cb][0];

        float a0 = 0.f, a1 = 0.f, a2 = 0.f, a3 = 0.f;
        const float* hl = hp + wLbase;
#pragma unroll
        for (int j = 0; j < 76; j += 4) {
            float4 hv = *(const float4*)(hl + j);
            a0 = fmaf(wl[j + 0], hv.x, a0);
            a1 = fmaf(wl[j + 1], hv.y, a1);
            a2 = fmaf(wl[j + 2], hv.z, a2);
            a3 = fmaf(wl[j + 3], hv.w, a3);
        }

        float uxn = 0.f;
        if (active && step + 1 < TT)
            uxn = __ldg(uxp + (size_t)(step + 1) * HH + o_g);

        {
            unsigned int v;
            do {
                asm volatile("ld.acquire.cluster.shared::cta.b32 %0, [%1];"
                             : "=r"(v) : "r"(my_fl) : "memory");
            } while (v < (unsigned int)step);
        }

        const float* hq = hp + wPbase;
#pragma unroll
        for (int j = 0; j < 76; j += 4) {
            float4 hv = *(const float4*)(hq + j);
            a0 = fmaf(wp[j + 0], hv.x, a0);
            a1 = fmaf(wp[j + 1], hv.y, a1);
            a2 = fmaf(wp[j + 2], hv.z, a2);
            a3 = fmaf(wp[j + 3], hv.w, a3);
        }
        float acc = (a0 + a1) + (a2 + a3);
        acc += __shfl_xor_sync(0xffffffffu, acc, 1);

        const int nb = cb ^ 1;
        if (active && half == 0) {
            hn = tanhf(acc + uxv);
            hbuf[nb][o_g] = hn;
            if (step + 1 < TT) {
                const uint32_t pdst = nb ? pdst1 : pdst0;
                asm volatile("st.shared::cluster.f32 [%0], %1;"
                             :: "r"(pdst), "f"(hn) : "memory");
            }
        }
        __syncthreads();
        if (t == 0 && step + 1 < TT) {
            asm volatile("st.release.cluster.shared::cluster.b32 [%0], %1;"
                         :: "r"(pfl), "r"((unsigned int)(step + 1)) : "memory");
        }
        uxv = uxn;
    }

    if (active && half == 0) g_h[b * HH + o_g] = hn;

    asm volatile("barrier.cluster.arrive.aligned;" ::: "memory");
    asm volatile("barrier.cluster.wait.aligned;"   ::: "memory");
}

// =====================================================================
// Kernel 3 (HMMA): out[b][v] = g_h[b]·Wout[v] + bout[v]
// M=64 (batch), N-tile=256 v per CTA, K=5x64 chunks.  Same split/layout/
// fragment machinery as k1.  8 warps: m-tile = w&3, n-half = w>>2.
// Epilogue uses SCALAR stores: out row pitch VV=50257 is odd, so float2
// stores are misaligned for odd batch rows (R16 crash).
// =====================================================================
#define K3_AH 0
#define K3_AL 9216              // 64*144
#define K3_BH 18432
#define K3_BL 55296             // 18432 + 256*144
#define K3_BYTES (92160 + 128)

__global__ void __launch_bounds__(256, 1) k_logits_mma(
    const float* __restrict__ Wout, const float* __restrict__ bout,
    float* __restrict__ out)
{
    extern __shared__ char dsm_raw[];

    const int t    = threadIdx.x;
    const int w    = t >> 5;
    const int lane = t & 31;
    const int r    = lane >> 2;
    const int tig  = lane & 3;
    const int v0   = blockIdx.x * 256;

    uintptr_t rawp = (uintptr_t)dsm_raw;
    char* dsm = dsm_raw + (((rawp + 127u) & ~(uintptr_t)127u) - rawp);

    const int mt = w & 3;        // m-tile (16 rows of the 64 batches)
    const int nh = w >> 2;       // n-half (128 v each)

    float acc[16][4];
#pragma unroll
    for (int nt = 0; nt < 16; nt++)
#pragma unroll
        for (int j = 0; j < 4; j++) acc[nt][j] = 0.f;

    for (int c = 0; c < 5; c++) {
        const int k0 = c * 64;
        __syncthreads();

        // ---- fill A (g_h rows 0..63, cols k0..k0+63) ----
        for (int idx = t; idx < 64 * 16; idx += 256) {
            const int row  = idx >> 4;
            const int c4   = idx & 15;
            const int gcol = k0 + c4 * 4;
            float4 v = make_float4(0.f, 0.f, 0.f, 0.f);
            if (gcol <= HH - 4)
                v = *(const float4*)(g_h + (size_t)row * HH + gcol);
            uint2 hi, lo;
            split4(v, hi, lo);
            const int off = row * PITCH_B + c4 * 8;
            *(uint2*)(dsm + K3_AH + off) = hi;
            *(uint2*)(dsm + K3_AL + off) = lo;
        }
        // ---- fill B (Wout rows v0..v0+255, cols k0..k0+63) ----
        for (int idx = t; idx < 256 * 16; idx += 256) {
            const int row  = idx >> 4;
            const int c4   = idx & 15;
            const int gcol = k0 + c4 * 4;
            const int vg   = v0 + row;
            float4 v = make_float4(0.f, 0.f, 0.f, 0.f);
            if (vg < VV && gcol <= HH - 4)
                v = *(const float4*)(Wout + (size_t)vg * HH + gcol);
            uint2 hi, lo;
            split4(v, hi, lo);
            const int off = row * PITCH_B + c4 * 8;
            *(uint2*)(dsm + K3_BH + off) = hi;
            *(uint2*)(dsm + K3_BL + off) = lo;
        }
        __syncthreads();

#pragma unroll
        for (int ks = 0; ks < 4; ks++) {
            const int koff = ks * 32 + tig * 4;
            const int arow = (mt * 16 + r) * PITCH_B;
            uint32_t ah[4], al[4];
            ah[0] = *(const uint32_t*)(dsm + K3_AH + arow + koff);
            ah[1] = *(const uint32_t*)(dsm + K3_AH + arow + 8 * PITCH_B + koff);
            ah[2] = *(const uint32_t*)(dsm + K3_AH + arow + koff + 16);
            ah[3] = *(const uint32_t*)(dsm + K3_AH + arow + 8 * PITCH_B + koff + 16);
            al[0] = *(const uint32_t*)(dsm + K3_AL + arow + koff);
            al[1] = *(const uint32_t*)(dsm + K3_AL + arow + 8 * PITCH_B + koff);
            al[2] = *(const uint32_t*)(dsm + K3_AL + arow + koff + 16);
            al[3] = *(const uint32_t*)(dsm + K3_AL + arow + 8 * PITCH_B + koff + 16);
#pragma unroll
            for (int nt = 0; nt < 16; nt++) {
                const int brow = ((nh * 16 + nt) * 8 + r) * PITCH_B;
                uint32_t bh0 = *(const uint32_t*)(dsm + K3_BH + brow + koff);
                uint32_t bh1 = *(const uint32_t*)(dsm + K3_BH + brow + koff + 16);
                uint32_t bl0 = *(const uint32_t*)(dsm + K3_BL + brow + koff);
                uint32_t bl1 = *(const uint32_t*)(dsm + K3_BL + brow + koff + 16);
                mma16816(acc[nt], ah, bh0, bh1);
                mma16816(acc[nt], al, bh0, bh1);
                mma16816(acc[nt], ah, bl0, bl1);
            }
        }
    }

    // ---- epilogue: add bias, write out (scalar stores; VV pitch is odd) ----
    const int row0 = mt * 16 + r;      // batch row (always < 64)
#pragma unroll
    for (int nt = 0; nt < 16; nt++) {
        const int col = v0 + (nh * 16 + nt) * 8 + 2 * tig;
        if (col < VV) {
            const float b0 = bout[col];
            out[(size_t)row0 * VV + col]       = acc[nt][0] + b0;
            out[(size_t)(row0 + 8) * VV + col] = acc[nt][2] + b0;
            if (col + 1 < VV) {
                const float b1 = bout[col + 1];
                out[(size_t)row0 * VV + col + 1]       = acc[nt][1] + b1;
                out[(size_t)(row0 + 8) * VV + col + 1] = acc[nt][3] + b1;
            }
        }
    }
}

// =====================================================================
extern "C" void kernel_launch(void* const* d_in, const int* in_sizes, int n_in,
                              void* d_out, int out_size)
{
    const float* ihs  = (const float*)d_in[0];
    const int*   tok  = (const int*)  d_in[1];
    const float* emb  = (const float*)d_in[2];
    const float* W    = (const float*)d_in[3];
    const float* U    = (const float*)d_in[4];
    const float* Wout = (const float*)d_in[5];
    const float* bout = (const float*)d_in[6];
    float* out = (float*)d_out;

    cudaFuncSetAttribute(k_embed_ux_mma,
                         cudaFuncAttributeMaxDynamicSharedMemorySize, K1_BYTES);
    cudaFuncSetAttribute(k_logits_mma,
                         cudaFuncAttributeMaxDynamicSharedMemorySize, K3_BYTES);

    k_embed_ux_mma<<<(BB * TT) / 128, 256, K1_BYTES>>>(tok, emb, U);
    k_scan<<<BB * 2, 320>>>(W, ihs);
    k_logits_mma<<<(VV + 255) / 256, 256, K3_BYTES>>>(Wout, bout, out);
}